// round 1
// baseline (speedup 1.0000x reference)
#include <cuda_runtime.h>
#include <mma.h>
#include <math.h>

using namespace nvcuda;

// Problem dims (fixed per reference)
#define B_ 4
#define L_ 8192
#define D_ 1024
#define M_ (B_ * L_)        // 32768 rows
#define N1_ (3 * D_)        // 3072
#define NC_ 64              // scan chunks
#define LC_ (L_ / NC_)      // 128 steps per chunk

// ---------------- scratch (static device arrays; no allocation) ----------------
__device__ float g_proj[(size_t)M_ * N1_];   // 402 MB: u|i|o pre-activation
__device__ float g_v[(size_t)M_ * D_];       // 128 MB: gated input i*tanh(u)
__device__ float g_o[(size_t)M_ * D_];       // 128 MB: sigmoid(o)
__device__ float g_y[(size_t)M_ * D_];       // 128 MB: o * s
__device__ float g_S[B_ * NC_ * D_];         // chunk-local final states
__device__ float g_init[B_ * NC_ * D_];      // chunk initial states

// ---------------- tf32 WMMA GEMM: C[M,N] = A[M,K] * B[N,K]^T ----------------
// Block tile 128x128, K-tile 32, 8 warps; warp tile 32x64 (2x4 wmma 16x16x8 frags).
#define GBM 128
#define GBN 128
#define GBK 32
#define GLD 36   // padded smem leading dim (multiple of 4 floats)

__global__ __launch_bounds__(256) void gemm_tf32_kernel(
    const float* __restrict__ A, const float* __restrict__ Bm, float* __restrict__ C,
    int M, int N, int K)
{
    __shared__ float As[GBM][GLD];
    __shared__ float Bs[GBN][GLD];

    const int tid    = threadIdx.x;
    const int warpId = tid >> 5;
    const int wm     = warpId & 3;   // 0..3 -> 32-row group
    const int wn     = warpId >> 2;  // 0..1 -> 64-col group
    const int bm     = blockIdx.y * GBM;
    const int bn     = blockIdx.x * GBN;

    wmma::fragment<wmma::accumulator, 16, 16, 8, float> acc[2][4];
#pragma unroll
    for (int i = 0; i < 2; i++)
#pragma unroll
        for (int j = 0; j < 4; j++)
            wmma::fill_fragment(acc[i][j], 0.0f);

    for (int k0 = 0; k0 < K; k0 += GBK) {
        // Stage A and B tiles (float4 coalesced loads, tf32-round into smem)
#pragma unroll
        for (int i = 0; i < 4; i++) {
            int f  = tid + i * 256;         // 0..1023 float4 slots (128 rows * 8 f4/row)
            int r  = f >> 3;
            int c4 = (f & 7) << 2;
            float4 av = *(const float4*)(A  + (size_t)(bm + r) * K + k0 + c4);
            As[r][c4 + 0] = wmma::__float_to_tf32(av.x);
            As[r][c4 + 1] = wmma::__float_to_tf32(av.y);
            As[r][c4 + 2] = wmma::__float_to_tf32(av.z);
            As[r][c4 + 3] = wmma::__float_to_tf32(av.w);
            float4 bv = *(const float4*)(Bm + (size_t)(bn + r) * K + k0 + c4);
            Bs[r][c4 + 0] = wmma::__float_to_tf32(bv.x);
            Bs[r][c4 + 1] = wmma::__float_to_tf32(bv.y);
            Bs[r][c4 + 2] = wmma::__float_to_tf32(bv.z);
            Bs[r][c4 + 3] = wmma::__float_to_tf32(bv.w);
        }
        __syncthreads();

#pragma unroll
        for (int kk = 0; kk < GBK; kk += 8) {
            wmma::fragment<wmma::matrix_a, 16, 16, 8, wmma::precision::tf32, wmma::row_major> af[2];
            wmma::fragment<wmma::matrix_b, 16, 16, 8, wmma::precision::tf32, wmma::col_major> bf[4];
#pragma unroll
            for (int i = 0; i < 2; i++)
                wmma::load_matrix_sync(af[i], &As[wm * 32 + i * 16][kk], GLD);
#pragma unroll
            for (int j = 0; j < 4; j++)
                wmma::load_matrix_sync(bf[j], &Bs[wn * 64 + j * 16][kk], GLD);
#pragma unroll
            for (int i = 0; i < 2; i++)
#pragma unroll
                for (int j = 0; j < 4; j++)
                    wmma::mma_sync(acc[i][j], af[i], bf[j], acc[i][j]);
        }
        __syncthreads();
    }

#pragma unroll
    for (int i = 0; i < 2; i++)
#pragma unroll
        for (int j = 0; j < 4; j++)
            wmma::store_matrix_sync(
                C + (size_t)(bm + wm * 32 + i * 16) * N + (bn + wn * 64 + j * 16),
                acc[i][j], N, wmma::mem_row_major);
}

// ---------------- pass A: activations + chunk-local scan ----------------
// One thread per (b, chunk, d): reads proj, writes v & o, accumulates local state.
__device__ __forceinline__ float sigf(float x) { return 1.0f / (1.0f + __expf(-x)); }

__global__ __launch_bounds__(256) void act_scan_kernel(const float* __restrict__ Adecay)
{
    int idx   = blockIdx.x * blockDim.x + threadIdx.x;   // [0, B_*NC_*D_)
    int d     = idx & (D_ - 1);
    int chunk = (idx >> 10) & (NC_ - 1);
    int b     = idx >> 16;

    float a = fminf(expf(Adecay[d]), 0.999f);
    float s = 0.0f;
    size_t rowbase = (size_t)b * L_ + (size_t)chunk * LC_;
#pragma unroll 4
    for (int t = 0; t < LC_; t++) {
        size_t row = rowbase + t;
        const float* p = g_proj + row * (size_t)N1_;
        float u  = tanhf(p[d]);
        float ii = sigf(p[D_ + d]);
        float oo = sigf(p[2 * D_ + d]);
        float v  = ii * u;
        g_v[row * D_ + d] = v;
        g_o[row * D_ + d] = oo;
        s = a * s + v;
    }
    g_S[idx] = s;
}

// ---------------- pass B: combine chunk states (tiny) ----------------
__global__ __launch_bounds__(256) void combine_kernel(const float* __restrict__ Adecay)
{
    int idx = blockIdx.x * blockDim.x + threadIdx.x;  // [0, B_*D_)
    int d = idx & (D_ - 1);
    int b = idx >> 10;
    float a  = fminf(expf(Adecay[d]), 0.999f);
    float aL = a;
#pragma unroll
    for (int i = 0; i < 7; i++) aL = aL * aL;         // a^128 (LC_ = 2^7)
    float carry = 0.0f;
    for (int c = 0; c < NC_; c++) {
        int off = (b * NC_ + c) * D_ + d;
        g_init[off] = carry;                           // state entering chunk c
        carry = aL * carry + g_S[off];
    }
}

// ---------------- pass C: final scan + output gate ----------------
__global__ __launch_bounds__(256) void finalize_kernel(const float* __restrict__ Adecay)
{
    int idx   = blockIdx.x * blockDim.x + threadIdx.x;
    int d     = idx & (D_ - 1);
    int chunk = (idx >> 10) & (NC_ - 1);
    int b     = idx >> 16;

    float a = fminf(expf(Adecay[d]), 0.999f);
    float s = g_init[idx];
    size_t rowbase = (size_t)b * L_ + (size_t)chunk * LC_;
#pragma unroll 4
    for (int t = 0; t < LC_; t++) {
        size_t off = (rowbase + t) * D_ + d;
        s = a * s + g_v[off];
        g_y[off] = g_o[off] * s;
    }
}

// ---------------- launch ----------------
extern "C" void kernel_launch(void* const* d_in, const int* in_sizes, int n_in,
                              void* d_out, int out_size)
{
    const float* x     = (const float*)d_in[0];   // [B,L,D]
    const float* W_in  = (const float*)d_in[1];   // [3D,D]
    const float* Adec  = (const float*)d_in[2];   // [D]
    const float* W_out = (const float*)d_in[3];   // [D,D]
    float* out = (float*)d_out;                   // [B,L,D]

    float *proj, *y;
    cudaGetSymbolAddress((void**)&proj, g_proj);
    cudaGetSymbolAddress((void**)&y, g_y);

    // GEMM1: proj = x * W_in^T  (M=32768, N=3072, K=1024)
    dim3 g1(N1_ / GBN, M_ / GBM);
    gemm_tf32_kernel<<<g1, 256>>>(x, W_in, proj, M_, N1_, D_);

    // activations + chunked scan
    act_scan_kernel<<<(B_ * NC_ * D_) / 256, 256>>>(Adec);
    combine_kernel<<<(B_ * D_) / 256, 256>>>(Adec);
    finalize_kernel<<<(B_ * NC_ * D_) / 256, 256>>>(Adec);

    // GEMM2: out = y * W_out^T  (M=32768, N=1024, K=1024)
    dim3 g2(D_ / GBN, M_ / GBM);
    gemm_tf32_kernel<<<g2, 256>>>(y, W_out, out, M_, D_, D_);
}

// round 16
// speedup vs baseline: 3.4529x; 3.4529x over previous
#include <cuda_runtime.h>
#include <cstdint>
#include <math.h>

// Problem dims (fixed)
#define B_ 4
#define L_ 8192
#define D_ 1024
#define M_ (B_ * L_)        // 32768
#define N1_ 3072
#define NC_ 64              // scan chunks
#define LC_ (L_ / NC_)      // 128
#define KTOT 1024
#define NKS 32              // K stages of 32

// ---------------- scratch (static device arrays; no allocation) ----------------
__device__ float g_x [(size_t)M_ * D_];      // tf32-rounded x
__device__ float g_wi[(size_t)N1_ * D_];     // tf32-rounded W_in
__device__ float g_wo[(size_t)D_ * D_];      // tf32-rounded W_out
__device__ float g_proj[(size_t)M_ * N1_];   // x @ W_in^T
__device__ float g_v[(size_t)M_ * D_];       // i*tanh(u)
__device__ float g_o[(size_t)M_ * D_];       // sigmoid(o)
__device__ float g_y[(size_t)M_ * D_];       // o*s (tf32-rounded)
__device__ float g_S[B_ * NC_ * D_];
__device__ float g_init[B_ * NC_ * D_];

// ---------------- helpers ----------------
__device__ __forceinline__ uint32_t smem_u32(const void* p) {
    uint32_t a;
    asm("{ .reg .u64 t; cvta.to.shared.u64 t, %1; cvt.u32.u64 %0, t; }" : "=r"(a) : "l"(p));
    return a;
}
__device__ __forceinline__ float to_tf32(float x) {
    uint32_t r;
    asm("cvt.rna.tf32.f32 %0, %1;" : "=r"(r) : "f"(x));
    return __uint_as_float(r);
}
#define CP_ASYNC(dst, src) \
    asm volatile("cp.async.cg.shared.global [%0], [%1], 16;" :: "r"(dst), "l"(src))
#define CP_COMMIT() asm volatile("cp.async.commit_group;")
#define CP_WAIT(n)  asm volatile("cp.async.wait_group %0;" :: "n"(n))

__device__ __forceinline__ void mma_tf32(float* c, const float* a, const float* b) {
    asm volatile(
        "mma.sync.aligned.m16n8k8.row.col.f32.tf32.tf32.f32 "
        "{%0,%1,%2,%3}, {%4,%5,%6,%7}, {%8,%9}, {%0,%1,%2,%3};"
        : "+f"(c[0]), "+f"(c[1]), "+f"(c[2]), "+f"(c[3])
        : "r"(__float_as_uint(a[0])), "r"(__float_as_uint(a[1])),
          "r"(__float_as_uint(a[2])), "r"(__float_as_uint(a[3])),
          "r"(__float_as_uint(b[0])), "r"(__float_as_uint(b[1])));
}

__device__ __forceinline__ float fsig(float x) { return __fdividef(1.0f, 1.0f + __expf(-x)); }
__device__ __forceinline__ float ftanh(float x) { return 2.0f * fsig(2.0f * x) - 1.0f; }

// ---------------- prep: RN-round inputs to tf32 (float4) ----------------
// layout: [x: 8388608 f4][W_in: 786432 f4][W_out: 262144 f4] = 9437184 f4
__global__ __launch_bounds__(256) void prep_kernel(const float* __restrict__ x,
                                                   const float* __restrict__ wi,
                                                   const float* __restrict__ wo) {
    int i = blockIdx.x * blockDim.x + threadIdx.x;
    const float4* src;
    float4* dst;
    int off;
    if (i < 8388608)        { src = (const float4*)x;  dst = (float4*)g_x;  off = i; }
    else if (i < 9175040)   { src = (const float4*)wi; dst = (float4*)g_wi; off = i - 8388608; }
    else                    { src = (const float4*)wo; dst = (float4*)g_wo; off = i - 9175040; }
    float4 v = src[off];
    v.x = to_tf32(v.x); v.y = to_tf32(v.y); v.z = to_tf32(v.z); v.w = to_tf32(v.w);
    dst[off] = v;
}

// ---------------- GEMM: C[M,N] = A[M,1024] @ B[N,1024]^T (tf32 mma.sync) ----------------
// 256 thr, tile 128x128, warp 64x32 (2m x 4n), 3-stage cp.async, K-stage 32.
// smem per stage: A 16KB + B 16KB; swizzle: (r*128 + k*4) ^ ((r&7)<<4).
__global__ __launch_bounds__(256, 2) void gemm_mma(const float* __restrict__ A,
                                                   const float* __restrict__ Bm,
                                                   float* __restrict__ C, int N) {
    extern __shared__ char smem[];
    const uint32_t sA = smem_u32(smem);
    const uint32_t sB = sA + 3 * 16384;
    const int tid  = threadIdx.x;
    const int wid  = tid >> 5;
    const int lane = tid & 31;
    const int wm   = wid & 1;          // 0..1
    const int wn   = wid >> 1;         // 0..3
    const int g    = lane >> 2;        // group 0..7
    const int t    = lane & 3;
    const uint32_t gx = (uint32_t)g << 4;   // swizzle XOR constant (r&7 == g)
    const int bm = blockIdx.y * 128;
    const int bn = blockIdx.x * 128;

    float acc[4][4][4];
#pragma unroll
    for (int i = 0; i < 4; i++)
#pragma unroll
        for (int j = 0; j < 4; j++)
#pragma unroll
            for (int k = 0; k < 4; k++) acc[i][j][k] = 0.0f;

    auto issue = [&](int buf, int kc) {
        const int k0 = kc * 32;
#pragma unroll
        for (int j = 0; j < 4; j++) {               // A tile: 1024 x 16B
            int idx = tid + j * 256;
            int r = idx >> 3, kg = idx & 7;
            const float* src = A + (size_t)(bm + r) * KTOT + k0 + kg * 4;
            uint32_t dst = sA + buf * 16384 +
                           (((uint32_t)(r * 128 + kg * 16)) ^ ((uint32_t)(r & 7) << 4));
            CP_ASYNC(dst, src);
        }
#pragma unroll
        for (int j = 0; j < 4; j++) {               // B tile
            int idx = tid + j * 256;
            int r = idx >> 3, kg = idx & 7;
            const float* src = Bm + (size_t)(bn + r) * KTOT + k0 + kg * 4;
            uint32_t dst = sB + buf * 16384 +
                           (((uint32_t)(r * 128 + kg * 16)) ^ ((uint32_t)(r & 7) << 4));
            CP_ASYNC(dst, src);
        }
        CP_COMMIT();
    };

    issue(0, 0);
    issue(1, 1);

    for (int kc = 0; kc < NKS; kc++) {
        if (kc < NKS - 2) { CP_WAIT(1); } else { CP_WAIT(0); }
        __syncthreads();
        if (kc + 2 < NKS) issue((kc + 2) % 3, kc + 2);

        const char* As = smem + ((kc % 3) * 16384);
        const char* Bs = smem + (3 * 16384 + (kc % 3) * 16384);
#pragma unroll
        for (int ks = 0; ks < 4; ks++) {
            const uint32_t kx0 = ((uint32_t)((ks * 8 + t) * 4)) ^ gx;
            const uint32_t kx1 = ((uint32_t)((ks * 8 + t + 4) * 4)) ^ gx;
            float a[4][4];
#pragma unroll
            for (int i = 0; i < 4; i++) {
                const char* base = As + (wm * 64 + i * 16 + g) * 128;
                a[i][0] = *(const float*)(base + kx0);
                a[i][1] = *(const float*)(base + 1024 + kx0);   // +8 rows
                a[i][2] = *(const float*)(base + kx1);
                a[i][3] = *(const float*)(base + 1024 + kx1);
            }
            float b[4][2];
#pragma unroll
            for (int j = 0; j < 4; j++) {
                const char* bb = Bs + (wn * 32 + j * 8 + g) * 128;
                b[j][0] = *(const float*)(bb + kx0);
                b[j][1] = *(const float*)(bb + kx1);
            }
#pragma unroll
            for (int i = 0; i < 4; i++)
#pragma unroll
                for (int j = 0; j < 4; j++)
                    mma_tf32(acc[i][j], a[i], b[j]);
        }
    }

    // epilogue: c0,c1 at (row, 2t), c2,c3 at (row+8, 2t)
#pragma unroll
    for (int i = 0; i < 4; i++) {
        int row = bm + wm * 64 + i * 16 + g;
#pragma unroll
        for (int j = 0; j < 4; j++) {
            int col = bn + wn * 32 + j * 8 + 2 * t;
            float* p0 = C + (size_t)row * N + col;
            float* p1 = C + (size_t)(row + 8) * N + col;
            *(float2*)p0 = make_float2(acc[i][j][0], acc[i][j][1]);
            *(float2*)p1 = make_float2(acc[i][j][2], acc[i][j][3]);
        }
    }
}

// ---------------- act + chunk-local scan ----------------
__global__ __launch_bounds__(256) void act_scan_kernel(const float* __restrict__ Adecay) {
    int idx   = blockIdx.x * blockDim.x + threadIdx.x;   // [0, B_*NC_*D_)
    int d     = idx & (D_ - 1);
    int chunk = (idx >> 10) & (NC_ - 1);
    int b     = idx >> 16;

    float a = fminf(expf(Adecay[d]), 0.999f);
    float s = 0.0f;
    size_t rowbase = (size_t)b * L_ + (size_t)chunk * LC_;
#pragma unroll 4
    for (int tt = 0; tt < LC_; tt++) {
        size_t row = rowbase + tt;
        const float* p = g_proj + row * (size_t)N1_;
        float u  = ftanh(p[d]);
        float ii = fsig(p[D_ + d]);
        float oo = fsig(p[2 * D_ + d]);
        float v  = ii * u;
        g_v[row * D_ + d] = v;
        g_o[row * D_ + d] = oo;
        s = a * s + v;
    }
    g_S[idx] = s;
}

// ---------------- combine chunk states ----------------
__global__ __launch_bounds__(256) void combine_kernel(const float* __restrict__ Adecay) {
    int idx = blockIdx.x * blockDim.x + threadIdx.x;  // [0, B_*D_)
    int d = idx & (D_ - 1);
    int b = idx >> 10;
    float a  = fminf(expf(Adecay[d]), 0.999f);
    float aL = a;
#pragma unroll
    for (int i = 0; i < 7; i++) aL = aL * aL;         // a^128
    float carry = 0.0f;
    for (int c = 0; c < NC_; c++) {
        int off = (b * NC_ + c) * D_ + d;
        g_init[off] = carry;
        carry = aL * carry + g_S[off];
    }
}

// ---------------- final scan + gate; store y tf32-rounded ----------------
__global__ __launch_bounds__(256) void finalize_kernel(const float* __restrict__ Adecay) {
    int idx   = blockIdx.x * blockDim.x + threadIdx.x;   // [0, B_*NC_*D_/4)
    int d4    = (idx & 255) << 2;
    int chunk = (idx >> 8) & (NC_ - 1);
    int b     = idx >> 14;

    float4 ad = *(const float4*)(Adecay + d4);
    float4 a;
    a.x = fminf(expf(ad.x), 0.999f); a.y = fminf(expf(ad.y), 0.999f);
    a.z = fminf(expf(ad.z), 0.999f); a.w = fminf(expf(ad.w), 0.999f);

    float4 s = *(const float4*)(g_init + ((b * NC_ + chunk) << 10) + d4);
    size_t base = ((size_t)b * L_ + (size_t)chunk * LC_) * D_ + d4;
#pragma unroll 4
    for (int tt = 0; tt < LC_; tt++) {
        size_t off = base + (size_t)tt * D_;
        float4 v = *(const float4*)(g_v + off);
        float4 o = *(const float4*)(g_o + off);
        s.x = a.x * s.x + v.x; s.y = a.y * s.y + v.y;
        s.z = a.z * s.z + v.z; s.w = a.w * s.w + v.w;
        float4 y;
        y.x = to_tf32(o.x * s.x); y.y = to_tf32(o.y * s.y);
        y.z = to_tf32(o.z * s.z); y.w = to_tf32(o.w * s.w);
        *(float4*)(g_y + off) = y;
    }
}

// ---------------- launch ----------------
extern "C" void kernel_launch(void* const* d_in, const int* in_sizes, int n_in,
                              void* d_out, int out_size) {
    const float* x     = (const float*)d_in[0];   // [B,L,D]
    const float* W_in  = (const float*)d_in[1];   // [3D,D]
    const float* Adec  = (const float*)d_in[2];   // [D]
    const float* W_out = (const float*)d_in[3];   // [D,D]
    float* out = (float*)d_out;                   // [B,L,D]

    float *xr, *wir, *wor, *proj, *y;
    cudaGetSymbolAddress((void**)&xr,   g_x);
    cudaGetSymbolAddress((void**)&wir,  g_wi);
    cudaGetSymbolAddress((void**)&wor,  g_wo);
    cudaGetSymbolAddress((void**)&proj, g_proj);
    cudaGetSymbolAddress((void**)&y,    g_y);

    const int SMEM = 6 * 16384;   // 96KB
    cudaFuncSetAttribute(gemm_mma, cudaFuncAttributeMaxDynamicSharedMemorySize, SMEM);

    // 0) round inputs to tf32
    prep_kernel<<<36864, 256>>>(x, W_in, W_out);

    // 1) proj = x @ W_in^T   (grid: n inner for L2 A-reuse)
    gemm_mma<<<dim3(N1_ / 128, M_ / 128), 256, SMEM>>>(xr, wir, proj, N1_);

    // 2) activations + chunk-local scan
    act_scan_kernel<<<(B_ * NC_ * D_) / 256, 256>>>(Adec);
    combine_kernel<<<(B_ * D_) / 256, 256>>>(Adec);
    finalize_kernel<<<(B_ * NC_ * D_) / 1024, 256>>>(Adec);

    // 3) out = y @ W_out^T
    gemm_mma<<<dim3(D_ / 128, M_ / 128), 256, SMEM>>>(y, wor, out, D_);
}